// round 2
// baseline (speedup 1.0000x reference)
#include <cuda_runtime.h>
#include <math.h>

// ---------------- problem constants ----------------
#define NN    8192            // nodes == seq len
#define INF_  512             // input feature
#define OUTF  256             // gcn out / lstm in
#define EDF   128             // edge attr dim
#define HID_  256             // lstm hidden
#define PPOOL (NN*(HID_/2))   // 1048576
#define LININ (2*PPOOL + 3*HID_) // 2097920

// ---------------- device scratch (no allocs allowed) ----------------
__device__ float    g_xw  [NN*OUTF];       // x @ W1^T
__device__ float    g_agg [NN*OUTF];       // scatter accumulator
__device__ float    g_seq [NN*OUTF];       // sigmoid(gcn)
__device__ float    g_deg [NN];
__device__ float    g_s2  [OUTF];          // rowsum of W2
__device__ float    g_xp0 [NN*4*HID_];     // seq @ W_ih0^T  (8192 x 1024)
__device__ float    g_h   [3][NN*HID_];    // per-layer hidden sequences
__device__ unsigned g_cnt [3*NN];          // per (layer, t) arrive counters
__device__ float    g_logits[3];

// ---------------- init (runs every replay) ----------------
__global__ void init_kernel() {
    int idx = blockIdx.x * blockDim.x + threadIdx.x;
    if (idx < NN*OUTF) g_agg[idx] = 0.f;
    if (idx < NN)      g_deg[idx] = 1.f;     // self loop
    if (idx < 3*NN)    g_cnt[idx] = 0u;
    if (idx < 3)       g_logits[idx] = 0.f;
}

__global__ void deg_kernel(const int* __restrict__ col, int E) {
    int e = blockIdx.x * blockDim.x + threadIdx.x;
    if (e < E) atomicAdd(&g_deg[col[e]], 1.f);
}

__global__ void s2_kernel(const float* __restrict__ W2) {
    int o = threadIdx.x;            // 256 threads
    float s = 0.f;
    for (int d = 0; d < EDF; d++) s += W2[o*EDF + d];
    g_s2[o] = s;
}

// ---------------- 128x128 SIMT SGEMM, C = A(MxK) * B(NxK)^T ----------------
// EPI 0: store C.  EPI 1: fused GCN message epilogue (tanh + norm + atomic scatter).
template<int EPI>
__global__ void sgemm128(const float* __restrict__ A, const float* __restrict__ B,
                         float* __restrict__ C, int M, int N, int K,
                         const int* __restrict__ rowi, const int* __restrict__ coli)
{
    __shared__ float As[16][132];
    __shared__ float Bs[16][132];
    __shared__ int   rowS[128], colS[128];
    __shared__ float normS[128];

    int t  = threadIdx.x;          // 0..255
    int bm = blockIdx.y, bn = blockIdx.x;
    int tx = t & 15, ty = t >> 4;

    if (EPI == 1) {
        if (t < 128) {
            int e = bm*128 + t;
            int r = rowi[e], c = coli[e];
            rowS[t] = r; colS[t] = c;
            normS[t] = rsqrtf(g_deg[r]) * rsqrtf(g_deg[c]);
        }
    }

    float acc[8][8];
#pragma unroll
    for (int i = 0; i < 8; i++)
#pragma unroll
        for (int j = 0; j < 8; j++) acc[i][j] = 0.f;

    for (int kc = 0; kc < K; kc += 16) {
        __syncthreads();
#pragma unroll
        for (int it = 0; it < 2; it++) {
            int q  = it*256 + t;     // 0..511
            int m  = q >> 2;         // 0..127
            int kk = (q & 3) << 2;   // 0,4,8,12
            float4 va = *(const float4*)&A[(size_t)(bm*128 + m)*K + kc + kk];
            As[kk+0][m] = va.x; As[kk+1][m] = va.y; As[kk+2][m] = va.z; As[kk+3][m] = va.w;
            float4 vb = *(const float4*)&B[(size_t)(bn*128 + m)*K + kc + kk];
            Bs[kk+0][m] = vb.x; Bs[kk+1][m] = vb.y; Bs[kk+2][m] = vb.z; Bs[kk+3][m] = vb.w;
        }
        __syncthreads();
#pragma unroll
        for (int kk = 0; kk < 16; kk++) {
            float a[8], b[8];
            *(float4*)&a[0] = *(float4*)&As[kk][ty*8];
            *(float4*)&a[4] = *(float4*)&As[kk][ty*8 + 4];
            *(float4*)&b[0] = *(float4*)&Bs[kk][tx*8];
            *(float4*)&b[4] = *(float4*)&Bs[kk][tx*8 + 4];
#pragma unroll
            for (int i = 0; i < 8; i++)
#pragma unroll
                for (int j = 0; j < 8; j++) acc[i][j] += a[i]*b[j];
        }
    }

    if (EPI == 0) {
#pragma unroll
        for (int i = 0; i < 8; i++) {
            size_t off = (size_t)(bm*128 + ty*8 + i)*N + bn*128 + tx*8;
            *(float4*)&C[off]     = make_float4(acc[i][0], acc[i][1], acc[i][2], acc[i][3]);
            *(float4*)&C[off + 4] = make_float4(acc[i][4], acc[i][5], acc[i][6], acc[i][7]);
        }
    } else {
#pragma unroll
        for (int i = 0; i < 8; i++) {
            int el = ty*8 + i;
            int r  = rowS[el], c = colS[el];
            float nm = normS[el];
            int o0 = bn*128 + tx*8;
            float4 x0 = *(const float4*)&g_xw[(size_t)r*OUTF + o0];
            float4 x1 = *(const float4*)&g_xw[(size_t)r*OUTF + o0 + 4];
            float xv[8] = {x0.x, x0.y, x0.z, x0.w, x1.x, x1.y, x1.z, x1.w};
#pragma unroll
            for (int j = 0; j < 8; j++) {
                float v = nm * tanhf(xv[j] * acc[i][j]);
                atomicAdd(&g_agg[(size_t)c*OUTF + o0 + j], v);
            }
        }
    }
}

// ---------------- self-loop + normalize + sigmoid ----------------
__global__ void seq_kernel(const float* __restrict__ bias) {
    int idx = blockIdx.x * blockDim.x + threadIdx.x;   // NN*OUTF threads
    int n = idx >> 8, o = idx & 255;
    float dg   = g_deg[n];
    float self = tanhf(g_xw[idx] * g_s2[o]) / dg;      // norm = dis^2 = 1/deg
    float v    = (g_agg[idx] + self) / dg + bias[o];
    g_seq[idx] = 1.f / (1.f + expf(-v));
}

// ---------------- LSTM persistent wavefront kernel ----------------
__device__ __forceinline__ void waitcnt(const unsigned* p, unsigned tgt) {
    unsigned v;
    do {
        asm volatile("ld.acquire.gpu.global.u32 %0, [%1];" : "=r"(v) : "l"(p) : "memory");
    } while (v < tgt);
}

extern __shared__ float smem_lstm[];

__global__ void lstm_kernel(const float* __restrict__ W_hh0,
                            const float* __restrict__ W_ih1, const float* __restrict__ W_hh1,
                            const float* __restrict__ W_ih2, const float* __restrict__ W_hh2)
{
    int b = blockIdx.x, tid = threadIdx.x;
    int layer, cidx, JSZ, COLS, C_self;
    if (b < 16)      { layer = 0; cidx = b;      JSZ = 16; COLS = 256; C_self = 16; }
    else if (b < 48) { layer = 1; cidx = b - 16; JSZ = 8;  COLS = 512; C_self = 32; }
    else             { layer = 2; cidx = b - 48; JSZ = 8;  COLS = 512; C_self = 32; }
    int ROWS  = 4 * JSZ;
    int jbase = cidx * JSZ;

    float* Wsm     = smem_lstm;            // 16384 floats
    float* v_s     = Wsm + 16384;          // 512
    float* gates_s = v_s + 512;            // 64
    float* c_s     = gates_s + 64;         // 16

    const float* Wih = (layer == 1) ? W_ih1 : W_ih2;
    const float* Whh = (layer == 0) ? W_hh0 : ((layer == 1) ? W_hh1 : W_hh2);

    // stage weights: row r = gate g * JSZ + jj  ->  global gate row g*256 + jbase + jj
    for (int idx = tid; idx < ROWS*COLS; idx += 256) {
        int r = idx / COLS, k = idx - r*COLS;
        int g = r / JSZ,  jj = r - g*JSZ;
        int R = g*256 + jbase + jj;
        float w;
        if (layer == 0)      w = Whh[(size_t)R*256 + k];
        else if (k < 256)    w = Wih[(size_t)R*256 + k];
        else                 w = Whh[(size_t)R*256 + (k - 256)];
        Wsm[idx] = w;
    }
    if (tid < 16) c_s[tid] = 0.f;
    __syncthreads();

    unsigned* cntL = g_cnt + layer*NN;
    unsigned* cntP = (layer > 0) ? (g_cnt + (layer-1)*NN) : (unsigned*)0;
    float* hOut       = g_h[layer];
    const float* hIn  = (layer > 0) ? g_h[layer-1] : (const float*)0;

    int warp = tid >> 5, lane = tid & 31;

    for (int t = 0; t < NN; t++) {
        if (tid == 0) {
            if (layer > 0) waitcnt(&cntP[t], (layer == 1) ? 16u : 32u);
            if (t > 0)     waitcnt(&cntL[t-1], (unsigned)C_self);
        }
        __syncthreads();

        // stage v = [h_below(t) ; h_self(t-1)]  (or just h_self(t-1) for layer 0)
        if (layer == 0) {
            v_s[tid] = (t > 0) ? g_h[0][(size_t)(t-1)*HID_ + tid] : 0.f;
        } else {
            v_s[tid]       = hIn[(size_t)t*HID_ + tid];
            v_s[256 + tid] = (t > 0) ? hOut[(size_t)(t-1)*HID_ + tid] : 0.f;
        }
        __syncthreads();

        if (layer == 0) {                 // 64 rows, 256 cols; 8 rows/warp
            float4 v0 = *(const float4*)&v_s[4*lane];
            float4 v1 = *(const float4*)&v_s[4*lane + 128];
#pragma unroll
            for (int i = 0; i < 8; i++) {
                int r = warp*8 + i;
                const float4* wp = (const float4*)&Wsm[r*256];
                float4 w0 = wp[lane], w1 = wp[lane + 32];
                float s = w0.x*v0.x + w0.y*v0.y + w0.z*v0.z + w0.w*v0.w
                        + w1.x*v1.x + w1.y*v1.y + w1.z*v1.z + w1.w*v1.w;
                s += __shfl_xor_sync(~0u, s, 16);
                s += __shfl_xor_sync(~0u, s, 8);
                s += __shfl_xor_sync(~0u, s, 4);
                s += __shfl_xor_sync(~0u, s, 2);
                s += __shfl_xor_sync(~0u, s, 1);
                if (lane == 0) {
                    int g = r >> 4, jj = r & 15;
                    s += g_xp0[(size_t)t*1024 + g*256 + jbase + jj];
                    gates_s[r] = s;
                }
            }
        } else {                           // 32 rows, 512 cols; 4 rows/warp
            float4 v0 = *(const float4*)&v_s[4*lane];
            float4 v1 = *(const float4*)&v_s[4*lane + 128];
            float4 v2 = *(const float4*)&v_s[4*lane + 256];
            float4 v3 = *(const float4*)&v_s[4*lane + 384];
#pragma unroll
            for (int i = 0; i < 4; i++) {
                int r = warp*4 + i;
                const float4* wp = (const float4*)&Wsm[r*512];
                float4 w0 = wp[lane], w1 = wp[lane+32], w2 = wp[lane+64], w3 = wp[lane+96];
                float s = w0.x*v0.x + w0.y*v0.y + w0.z*v0.z + w0.w*v0.w
                        + w1.x*v1.x + w1.y*v1.y + w1.z*v1.z + w1.w*v1.w
                        + w2.x*v2.x + w2.y*v2.y + w2.z*v2.z + w2.w*v2.w
                        + w3.x*v3.x + w3.y*v3.y + w3.z*v3.z + w3.w*v3.w;
                s += __shfl_xor_sync(~0u, s, 16);
                s += __shfl_xor_sync(~0u, s, 8);
                s += __shfl_xor_sync(~0u, s, 4);
                s += __shfl_xor_sync(~0u, s, 2);
                s += __shfl_xor_sync(~0u, s, 1);
                if (lane == 0) gates_s[r] = s;
            }
        }
        __syncthreads();

        if (tid < JSZ) {
            float ip = gates_s[tid],         fp = gates_s[JSZ + tid];
            float gp = gates_s[2*JSZ + tid], op = gates_s[3*JSZ + tid];
            float ig = 1.f / (1.f + expf(-ip));
            float fg = 1.f / (1.f + expf(-fp));
            float gg = tanhf(gp);
            float og = 1.f / (1.f + expf(-op));
            float c  = fg * c_s[tid] + ig * gg;
            c_s[tid] = c;
            hOut[(size_t)t*HID_ + jbase + tid] = og * tanhf(c);
        }
        __syncthreads();

        if (tid == 0) {
            asm volatile("red.release.gpu.global.add.u32 [%0], %1;"
                         :: "l"(&cntL[t]), "r"(1u) : "memory");
        }
    }
}

// ---------------- pooling + big linear (main 2P terms) ----------------
__global__ void pool_lin_kernel(const float* __restrict__ linW) {
    __shared__ float s0[8], s1[8], s2b[8];
    int tid = threadIdx.x;
    float p0 = 0.f, p1 = 0.f, p2 = 0.f;
#pragma unroll
    for (int it = 0; it < 2; it++) {
        size_t i = (size_t)blockIdx.x*512 + it*256 + tid;   // i < PPOOL
        int l = (int)(i >> 7), q = (int)(i & 127);
        float a  = g_h[2][(size_t)l*HID_ + 2*q];
        float bb = g_h[2][(size_t)l*HID_ + 2*q + 1];
        float mx = fmaxf(a, bb), av = 0.5f*(a + bb);
        p0 += linW[i]*mx                    + linW[(size_t)PPOOL + i]*av;
        p1 += linW[(size_t)LININ + i]*mx    + linW[(size_t)LININ + PPOOL + i]*av;
        p2 += linW[2*(size_t)LININ + i]*mx  + linW[2*(size_t)LININ + PPOOL + i]*av;
    }
    int lane = tid & 31, w = tid >> 5;
#pragma unroll
    for (int o = 16; o > 0; o >>= 1) {
        p0 += __shfl_xor_sync(~0u, p0, o);
        p1 += __shfl_xor_sync(~0u, p1, o);
        p2 += __shfl_xor_sync(~0u, p2, o);
    }
    if (lane == 0) { s0[w] = p0; s1[w] = p1; s2b[w] = p2; }
    __syncthreads();
    if (tid == 0) {
        float a = 0.f, bb = 0.f, c = 0.f;
        for (int i = 0; i < 8; i++) { a += s0[i]; bb += s1[i]; c += s2b[i]; }
        atomicAdd(&g_logits[0], a);
        atomicAdd(&g_logits[1], bb);
        atomicAdd(&g_logits[2], c);
    }
}

// ---------------- tail (hT terms) + bias + softmax ----------------
__global__ void final_kernel(const float* __restrict__ linW, const float* __restrict__ linb,
                             float* __restrict__ out) {
    __shared__ float s0[8], s1[8], s2b[8];
    int tid = threadIdx.x;       // 256 threads
    float h0T = g_h[0][(size_t)(NN-1)*HID_ + tid];
    float h1T = g_h[1][(size_t)(NN-1)*HID_ + tid];
    float h2T = g_h[2][(size_t)(NN-1)*HID_ + tid];
    size_t base = 2*(size_t)PPOOL;
    float p0 = linW[base + tid]*h0T + linW[base + 256 + tid]*h1T + linW[base + 512 + tid]*h2T;
    size_t b1 = (size_t)LININ + base;
    float p1 = linW[b1 + tid]*h0T + linW[b1 + 256 + tid]*h1T + linW[b1 + 512 + tid]*h2T;
    size_t b2 = 2*(size_t)LININ + base;
    float p2 = linW[b2 + tid]*h0T + linW[b2 + 256 + tid]*h1T + linW[b2 + 512 + tid]*h2T;

    int lane = tid & 31, w = tid >> 5;
#pragma unroll
    for (int o = 16; o > 0; o >>= 1) {
        p0 += __shfl_xor_sync(~0u, p0, o);
        p1 += __shfl_xor_sync(~0u, p1, o);
        p2 += __shfl_xor_sync(~0u, p2, o);
    }
    if (lane == 0) { s0[w] = p0; s1[w] = p1; s2b[w] = p2; }
    __syncthreads();
    if (tid == 0) {
        float a = 0.f, bb = 0.f, c = 0.f;
        for (int i = 0; i < 8; i++) { a += s0[i]; bb += s1[i]; c += s2b[i]; }
        float l0 = g_logits[0] + a  + linb[0];
        float l1 = g_logits[1] + bb + linb[1];
        float l2 = g_logits[2] + c  + linb[2];
        float m  = fmaxf(l0, fmaxf(l1, l2));
        float e0 = expf(l0 - m), e1 = expf(l1 - m), e2 = expf(l2 - m);
        float inv = 1.f / (e0 + e1 + e2);
        out[0] = e0*inv; out[1] = e1*inv; out[2] = e2*inv;
    }
}

// ---------------- launch ----------------
extern "C" void kernel_launch(void* const* d_in, const int* in_sizes, int n_in,
                              void* d_out, int out_size)
{
    const float* x      = (const float*)d_in[0];
    const int*   ei     = (const int*)  d_in[1];
    const float* ea     = (const float*)d_in[2];
    const float* W1     = (const float*)d_in[3];
    const float* W2     = (const float*)d_in[4];
    const float* bias   = (const float*)d_in[5];
    const float* W_ih0  = (const float*)d_in[6];
    const float* W_hh0  = (const float*)d_in[7];
    const float* W_ih1  = (const float*)d_in[8];
    const float* W_hh1  = (const float*)d_in[9];
    const float* W_ih2  = (const float*)d_in[10];
    const float* W_hh2  = (const float*)d_in[11];
    const float* linW   = (const float*)d_in[12];
    const float* linb   = (const float*)d_in[13];
    float* out = (float*)d_out;

    int E = in_sizes[1] / 2;
    const int* rowI = ei;
    const int* colI = ei + E;

    static int smem_bytes = 120 * 1024;
    cudaFuncSetAttribute((const void*)lstm_kernel,
                         cudaFuncAttributeMaxDynamicSharedMemorySize, smem_bytes);

    void *p_xw, *p_seq, *p_xp0;
    cudaGetSymbolAddress(&p_xw,  g_xw);
    cudaGetSymbolAddress(&p_seq, g_seq);
    cudaGetSymbolAddress(&p_xp0, g_xp0);

    // 1. init scratch
    init_kernel<<<NN, 256>>>();
    // 2. degrees (self loop pre-seeded to 1)
    deg_kernel<<<(E + 255) / 256, 256>>>(colI, E);
    // 3. W2 row sums (self-loop edge attr = ones)
    s2_kernel<<<1, 256>>>(W2);
    // 4. xw = x @ W1^T   [8192 x 256]
    sgemm128<0><<<dim3(OUTF/128, NN/128), 256>>>(x, W1, (float*)p_xw, NN, OUTF, INF_, 0, 0);
    // 5. fused edge GEMM + tanh + norm + scatter
    sgemm128<1><<<dim3(OUTF/128, E/128), 256>>>(ea, W2, 0, E, OUTF, EDF, rowI, colI);
    // 6. self loops + mean + bias + sigmoid -> seq
    seq_kernel<<<NN*OUTF/256, 256>>>(bias);
    // 7. xp0 = seq @ W_ih0^T   [8192 x 1024]
    sgemm128<0><<<dim3(4*HID_/128, NN/128), 256>>>((const float*)p_seq, W_ih0, (float*)p_xp0,
                                                   NN, 4*HID_, OUTF, 0, 0);
    // 8. persistent pipelined LSTM (16 + 32 + 32 CTAs)
    lstm_kernel<<<80, 256, smem_bytes>>>(W_hh0, W_ih1, W_hh1, W_ih2, W_hh2);
    // 9. pooling + big linear
    pool_lin_kernel<<<PPOOL/512, 256>>>(linW);
    // 10. tail + softmax
    final_kernel<<<1, 256>>>(linW, linb, out);
}

// round 3
// speedup vs baseline: 1.1777x; 1.1777x over previous
#include <cuda_runtime.h>
#include <math.h>

// ---------------- problem constants ----------------
#define NN    8192            // nodes == seq len
#define INF_  512             // input feature
#define OUTF  256             // gcn out / lstm in
#define EDF   128             // edge attr dim
#define HID_  256             // lstm hidden
#define PPOOL (NN*(HID_/2))   // 1048576
#define LININ (2*PPOOL + 3*HID_) // 2097920

// ---------------- device scratch (no allocs allowed) ----------------
__device__ float    g_xw  [NN*OUTF];       // x @ W1^T
__device__ float    g_agg [NN*OUTF];       // scatter accumulator
__device__ float    g_seq [NN*OUTF];       // sigmoid(gcn)
__device__ float    g_deg [NN];
__device__ float    g_s2  [OUTF];          // rowsum of W2
__device__ float    g_xp0 [NN*4*HID_];     // seq @ W_ih0^T  (8192 x 1024)
__device__ float    g_h   [3][NN*HID_];    // per-layer hidden sequences
__device__ unsigned g_cnt [3*NN];          // per (layer, t) warp-arrive counters
__device__ float    g_logits[3];

// ---------------- fast activations (clamped, ~1e-6 rel err) ----------------
__device__ __forceinline__ float sigf(float x) {
    return __fdividef(1.f, 1.f + __expf(-x));
}
__device__ __forceinline__ float tanhfast(float x) {
    x = fminf(fmaxf(x, -15.f), 15.f);
    float e = __expf(2.f * x);
    return __fdividef(e - 1.f, e + 1.f);
}

// ---------------- sync primitives ----------------
__device__ __forceinline__ void waitcnt(const unsigned* p, unsigned tgt) {
    unsigned v;
    do {
        asm volatile("ld.acquire.gpu.global.u32 %0, [%1];" : "=r"(v) : "l"(p) : "memory");
    } while (v < tgt);
}
__device__ __forceinline__ void waitcnt2(const unsigned* a, const unsigned* b, unsigned tgt) {
    unsigned va, vb;
    do {
        asm volatile("ld.acquire.gpu.global.u32 %0, [%1];" : "=r"(va) : "l"(a) : "memory");
        asm volatile("ld.acquire.gpu.global.u32 %0, [%1];" : "=r"(vb) : "l"(b) : "memory");
    } while (va < tgt || vb < tgt);
}
__device__ __forceinline__ void relinc(unsigned* p) {
    asm volatile("red.release.gpu.global.add.u32 [%0], %1;" :: "l"(p), "r"(1u) : "memory");
}

// ---------------- init (runs every replay) ----------------
__global__ void init_kernel() {
    int idx = blockIdx.x * blockDim.x + threadIdx.x;
    if (idx < NN*OUTF) g_agg[idx] = 0.f;
    if (idx < NN)      g_deg[idx] = 1.f;     // self loop
    if (idx < 3*NN)    g_cnt[idx] = 0u;
    if (idx < 3)       g_logits[idx] = 0.f;
}

__global__ void deg_kernel(const int* __restrict__ col, int E) {
    int e = blockIdx.x * blockDim.x + threadIdx.x;
    if (e < E) atomicAdd(&g_deg[col[e]], 1.f);
}

__global__ void s2_kernel(const float* __restrict__ W2) {
    int o = threadIdx.x;            // 256 threads
    float s = 0.f;
    for (int d = 0; d < EDF; d++) s += W2[o*EDF + d];
    g_s2[o] = s;
}

// ---------------- 128x128 SIMT SGEMM, C = A(MxK) * B(NxK)^T ----------------
// EPI 0: store C.  EPI 1: fused GCN message epilogue (tanh + norm + atomic scatter).
template<int EPI>
__global__ void sgemm128(const float* __restrict__ A, const float* __restrict__ B,
                         float* __restrict__ C, int M, int N, int K,
                         const int* __restrict__ rowi, const int* __restrict__ coli)
{
    __shared__ float As[16][132];
    __shared__ float Bs[16][132];
    __shared__ int   rowS[128], colS[128];
    __shared__ float normS[128];

    int t  = threadIdx.x;          // 0..255
    int bm = blockIdx.y, bn = blockIdx.x;
    int tx = t & 15, ty = t >> 4;

    if (EPI == 1) {
        if (t < 128) {
            int e = bm*128 + t;
            int r = rowi[e], c = coli[e];
            rowS[t] = r; colS[t] = c;
            normS[t] = rsqrtf(g_deg[r]) * rsqrtf(g_deg[c]);
        }
    }

    float acc[8][8];
#pragma unroll
    for (int i = 0; i < 8; i++)
#pragma unroll
        for (int j = 0; j < 8; j++) acc[i][j] = 0.f;

    for (int kc = 0; kc < K; kc += 16) {
        __syncthreads();
#pragma unroll
        for (int it = 0; it < 2; it++) {
            int q  = it*256 + t;     // 0..511
            int m  = q >> 2;         // 0..127
            int kk = (q & 3) << 2;   // 0,4,8,12
            float4 va = *(const float4*)&A[(size_t)(bm*128 + m)*K + kc + kk];
            As[kk+0][m] = va.x; As[kk+1][m] = va.y; As[kk+2][m] = va.z; As[kk+3][m] = va.w;
            float4 vb = *(const float4*)&B[(size_t)(bn*128 + m)*K + kc + kk];
            Bs[kk+0][m] = vb.x; Bs[kk+1][m] = vb.y; Bs[kk+2][m] = vb.z; Bs[kk+3][m] = vb.w;
        }
        __syncthreads();
#pragma unroll
        for (int kk = 0; kk < 16; kk++) {
            float a[8], b[8];
            *(float4*)&a[0] = *(float4*)&As[kk][ty*8];
            *(float4*)&a[4] = *(float4*)&As[kk][ty*8 + 4];
            *(float4*)&b[0] = *(float4*)&Bs[kk][tx*8];
            *(float4*)&b[4] = *(float4*)&Bs[kk][tx*8 + 4];
#pragma unroll
            for (int i = 0; i < 8; i++)
#pragma unroll
                for (int j = 0; j < 8; j++) acc[i][j] += a[i]*b[j];
        }
    }

    if (EPI == 0) {
#pragma unroll
        for (int i = 0; i < 8; i++) {
            size_t off = (size_t)(bm*128 + ty*8 + i)*N + bn*128 + tx*8;
            *(float4*)&C[off]     = make_float4(acc[i][0], acc[i][1], acc[i][2], acc[i][3]);
            *(float4*)&C[off + 4] = make_float4(acc[i][4], acc[i][5], acc[i][6], acc[i][7]);
        }
    } else {
#pragma unroll
        for (int i = 0; i < 8; i++) {
            int el = ty*8 + i;
            int r  = rowS[el], c = colS[el];
            float nm = normS[el];
            int o0 = bn*128 + tx*8;
            float4 x0 = *(const float4*)&g_xw[(size_t)r*OUTF + o0];
            float4 x1 = *(const float4*)&g_xw[(size_t)r*OUTF + o0 + 4];
            float xv[8] = {x0.x, x0.y, x0.z, x0.w, x1.x, x1.y, x1.z, x1.w};
#pragma unroll
            for (int j = 0; j < 8; j++) {
                float v = nm * tanhfast(xv[j] * acc[i][j]);
                atomicAdd(&g_agg[(size_t)c*OUTF + o0 + j], v);
            }
        }
    }
}

// ---------------- self-loop + normalize + sigmoid ----------------
__global__ void seq_kernel(const float* __restrict__ bias) {
    int idx = blockIdx.x * blockDim.x + threadIdx.x;   // NN*OUTF threads
    int n = idx >> 8, o = idx & 255;
    float dg   = g_deg[n];
    float self = tanhfast(g_xw[idx] * g_s2[o]) / dg;   // norm = dis^2 = 1/deg
    float v    = (g_agg[idx] + self) / dg + bias[o];
    g_seq[idx] = sigf(v);
}

// ---------------- LSTM: warp-autonomous wavefront, weights in registers ----
// 80 CTAs x 256 threads. CTAs 0..15: layer 0 (each warp owns 2 hidden units).
// CTAs 16..47: layer 1, CTAs 48..79: layer 2 (each warp owns 1 hidden unit,
// 4 gate rows of 512 fused [W_ih | W_hh] columns).
// Per-(layer,t) counters count producing WARP-lanes; all targets are 256.
__global__ void __launch_bounds__(256, 1) lstm_kernel(
    const float* __restrict__ W_hh0,
    const float* __restrict__ W_ih1, const float* __restrict__ W_hh1,
    const float* __restrict__ W_ih2, const float* __restrict__ W_hh2)
{
    int b = blockIdx.x;
    int tid = threadIdx.x, warp = tid >> 5, lane = tid & 31;

    if (b < 16) {
        // ---------------- layer 0: 2 units per warp ----------------
        const int jA = b*16 + warp*2;
        float w[8][8];                      // row r = u*4+g, 8 cols per lane
#pragma unroll
        for (int u = 0; u < 2; u++)
#pragma unroll
        for (int g = 0; g < 4; g++) {
            const float* p = &W_hh0[(size_t)(g*256 + jA + u)*256 + 8*lane];
            float4 a = *(const float4*)p, c4 = *(const float4*)(p + 4);
            w[u*4+g][0]=a.x;  w[u*4+g][1]=a.y;  w[u*4+g][2]=a.z;  w[u*4+g][3]=a.w;
            w[u*4+g][4]=c4.x; w[u*4+g][5]=c4.y; w[u*4+g][6]=c4.z; w[u*4+g][7]=c4.w;
        }
        unsigned* cnt0 = g_cnt;
        const int jMe = jA + ((lane < 2) ? lane : 0);
        float cst = 0.f;

        for (int t = 0; t < NN; t++) {
            float xp[4];
            if (lane < 2) {                 // prefetch xp0 before the poll
#pragma unroll
                for (int g = 0; g < 4; g++)
                    xp[g] = g_xp0[(size_t)t*1024 + g*256 + jMe];
            }
            float acc[8];
#pragma unroll
            for (int r = 0; r < 8; r++) acc[r] = 0.f;
            if (t > 0) {
                waitcnt(&cnt0[t-1], 256u);
                const float* hp = &g_h[0][(size_t)(t-1)*256 + 8*lane];
                float4 a = *(const float4*)hp, c4 = *(const float4*)(hp + 4);
                float v[8] = {a.x, a.y, a.z, a.w, c4.x, c4.y, c4.z, c4.w};
#pragma unroll
                for (int r = 0; r < 8; r++)
#pragma unroll
                for (int m = 0; m < 8; m++) acc[r] += w[r][m]*v[m];
            }
#pragma unroll
            for (int r = 0; r < 8; r++)
#pragma unroll
            for (int o = 16; o > 0; o >>= 1)
                acc[r] += __shfl_xor_sync(0xffffffffu, acc[r], o);

            if (lane < 2) {
                float i_ = sigf(acc[lane*4+0] + xp[0]);
                float f_ = sigf(acc[lane*4+1] + xp[1]);
                float g_ = tanhfast(acc[lane*4+2] + xp[2]);
                float o_ = sigf(acc[lane*4+3] + xp[3]);
                cst = f_*cst + i_*g_;
                g_h[0][(size_t)t*256 + jMe] = o_*tanhfast(cst);
                relinc(&cnt0[t]);
            }
        }
    } else {
        // ---------------- layers 1,2: 1 unit per warp ----------------
        int layer = (b < 48) ? 1 : 2;
        int cidx  = (b < 48) ? b - 16 : b - 48;
        int j     = cidx*8 + warp;
        const float* Wih = (layer == 1) ? W_ih1 : W_ih2;
        const float* Whh = (layer == 1) ? W_hh1 : W_hh2;

        float w[4][16];                     // 4 gate rows x 16 cols per lane
#pragma unroll
        for (int g = 0; g < 4; g++) {
            const float* p = (lane < 16)
                ? &Wih[(size_t)(g*256 + j)*256 + 16*lane]
                : &Whh[(size_t)(g*256 + j)*256 + 16*(lane - 16)];
#pragma unroll
            for (int q = 0; q < 4; q++) {
                float4 a = *(const float4*)(p + 4*q);
                w[g][4*q+0]=a.x; w[g][4*q+1]=a.y; w[g][4*q+2]=a.z; w[g][4*q+3]=a.w;
            }
        }
        unsigned* cntS = g_cnt + layer*NN;
        unsigned* cntB = g_cnt + (layer-1)*NN;
        const float* hIn = g_h[layer-1];
        float*       hOut = g_h[layer];
        float cst = 0.f;

        for (int t = 0; t < NN; t++) {
            if (t > 0) waitcnt2(&cntS[t-1], &cntB[t], 256u);
            else       waitcnt(&cntB[0], 256u);

            float v[16];
            bool zero = (lane >= 16) && (t == 0);
            const float* vp = (lane < 16)
                ? &hIn[(size_t)t*256 + 16*lane]
                : &hOut[(size_t)(t-1)*256 + 16*(lane - 16)];
            if (!zero) {
#pragma unroll
                for (int q = 0; q < 4; q++) {
                    float4 a = *(const float4*)(vp + 4*q);
                    v[4*q+0]=a.x; v[4*q+1]=a.y; v[4*q+2]=a.z; v[4*q+3]=a.w;
                }
            } else {
#pragma unroll
                for (int m = 0; m < 16; m++) v[m] = 0.f;
            }

            float acc[4] = {0.f, 0.f, 0.f, 0.f};
#pragma unroll
            for (int g = 0; g < 4; g++)
#pragma unroll
            for (int m = 0; m < 16; m++) acc[g] += w[g][m]*v[m];
#pragma unroll
            for (int g = 0; g < 4; g++)
#pragma unroll
            for (int o = 16; o > 0; o >>= 1)
                acc[g] += __shfl_xor_sync(0xffffffffu, acc[g], o);

            if (lane == 0) {
                float i_ = sigf(acc[0]), f_ = sigf(acc[1]);
                float g_ = tanhfast(acc[2]), o_ = sigf(acc[3]);
                cst = f_*cst + i_*g_;
                hOut[(size_t)t*256 + j] = o_*tanhfast(cst);
                relinc(&cntS[t]);
                relinc(&cntS[t]);   // 2 increments: keeps all targets at 256
            }
        }
    }
}

// ---------------- pooling + big linear (main 2P terms) ----------------
__global__ void pool_lin_kernel(const float* __restrict__ linW) {
    __shared__ float s0[8], s1[8], s2b[8];
    int tid = threadIdx.x;
    float p0 = 0.f, p1 = 0.f, p2 = 0.f;
#pragma unroll
    for (int it = 0; it < 2; it++) {
        size_t i = (size_t)blockIdx.x*512 + it*256 + tid;   // i < PPOOL
        int l = (int)(i >> 7), q = (int)(i & 127);
        float a  = g_h[2][(size_t)l*HID_ + 2*q];
        float bb = g_h[2][(size_t)l*HID_ + 2*q + 1];
        float mx = fmaxf(a, bb), av = 0.5f*(a + bb);
        p0 += linW[i]*mx                    + linW[(size_t)PPOOL + i]*av;
        p1 += linW[(size_t)LININ + i]*mx    + linW[(size_t)LININ + PPOOL + i]*av;
        p2 += linW[2*(size_t)LININ + i]*mx  + linW[2*(size_t)LININ + PPOOL + i]*av;
    }
    int lane = tid & 31, w = tid >> 5;
#pragma unroll
    for (int o = 16; o > 0; o >>= 1) {
        p0 += __shfl_xor_sync(~0u, p0, o);
        p1 += __shfl_xor_sync(~0u, p1, o);
        p2 += __shfl_xor_sync(~0u, p2, o);
    }
    if (lane == 0) { s0[w] = p0; s1[w] = p1; s2b[w] = p2; }
    __syncthreads();
    if (tid == 0) {
        float a = 0.f, bb = 0.f, c = 0.f;
        for (int i = 0; i < 8; i++) { a += s0[i]; bb += s1[i]; c += s2b[i]; }
        atomicAdd(&g_logits[0], a);
        atomicAdd(&g_logits[1], bb);
        atomicAdd(&g_logits[2], c);
    }
}

// ---------------- tail (hT terms) + bias + softmax ----------------
__global__ void final_kernel(const float* __restrict__ linW, const float* __restrict__ linb,
                             float* __restrict__ out) {
    __shared__ float s0[8], s1[8], s2b[8];
    int tid = threadIdx.x;       // 256 threads
    float h0T = g_h[0][(size_t)(NN-1)*HID_ + tid];
    float h1T = g_h[1][(size_t)(NN-1)*HID_ + tid];
    float h2T = g_h[2][(size_t)(NN-1)*HID_ + tid];
    size_t base = 2*(size_t)PPOOL;
    float p0 = linW[base + tid]*h0T + linW[base + 256 + tid]*h1T + linW[base + 512 + tid]*h2T;
    size_t b1 = (size_t)LININ + base;
    float p1 = linW[b1 + tid]*h0T + linW[b1 + 256 + tid]*h1T + linW[b1 + 512 + tid]*h2T;
    size_t b2 = 2*(size_t)LININ + base;
    float p2 = linW[b2 + tid]*h0T + linW[b2 + 256 + tid]*h1T + linW[b2 + 512 + tid]*h2T;

    int lane = tid & 31, w = tid >> 5;
#pragma unroll
    for (int o = 16; o > 0; o >>= 1) {
        p0 += __shfl_xor_sync(~0u, p0, o);
        p1 += __shfl_xor_sync(~0u, p1, o);
        p2 += __shfl_xor_sync(~0u, p2, o);
    }
    if (lane == 0) { s0[w] = p0; s1[w] = p1; s2b[w] = p2; }
    __syncthreads();
    if (tid == 0) {
        float a = 0.f, bb = 0.f, c = 0.f;
        for (int i = 0; i < 8; i++) { a += s0[i]; bb += s1[i]; c += s2b[i]; }
        float l0 = g_logits[0] + a  + linb[0];
        float l1 = g_logits[1] + bb + linb[1];
        float l2 = g_logits[2] + c  + linb[2];
        float m  = fmaxf(l0, fmaxf(l1, l2));
        float e0 = expf(l0 - m), e1 = expf(l1 - m), e2 = expf(l2 - m);
        float inv = 1.f / (e0 + e1 + e2);
        out[0] = e0*inv; out[1] = e1*inv; out[2] = e2*inv;
    }
}

// ---------------- launch ----------------
extern "C" void kernel_launch(void* const* d_in, const int* in_sizes, int n_in,
                              void* d_out, int out_size)
{
    const float* x      = (const float*)d_in[0];
    const int*   ei     = (const int*)  d_in[1];
    const float* ea     = (const float*)d_in[2];
    const float* W1     = (const float*)d_in[3];
    const float* W2     = (const float*)d_in[4];
    const float* bias   = (const float*)d_in[5];
    const float* W_ih0  = (const float*)d_in[6];
    const float* W_hh0  = (const float*)d_in[7];
    const float* W_ih1  = (const float*)d_in[8];
    const float* W_hh1  = (const float*)d_in[9];
    const float* W_ih2  = (const float*)d_in[10];
    const float* W_hh2  = (const float*)d_in[11];
    const float* linW   = (const float*)d_in[12];
    const float* linb   = (const float*)d_in[13];
    float* out = (float*)d_out;

    int E = in_sizes[1] / 2;
    const int* rowI = ei;
    const int* colI = ei + E;

    void *p_xw, *p_seq, *p_xp0;
    cudaGetSymbolAddress(&p_xw,  g_xw);
    cudaGetSymbolAddress(&p_seq, g_seq);
    cudaGetSymbolAddress(&p_xp0, g_xp0);

    // 1. init scratch
    init_kernel<<<NN, 256>>>();
    // 2. degrees (self loop pre-seeded to 1)
    deg_kernel<<<(E + 255) / 256, 256>>>(colI, E);
    // 3. W2 row sums (self-loop edge attr = ones)
    s2_kernel<<<1, 256>>>(W2);
    // 4. xw = x @ W1^T   [8192 x 256]
    sgemm128<0><<<dim3(OUTF/128, NN/128), 256>>>(x, W1, (float*)p_xw, NN, OUTF, INF_, 0, 0);
    // 5. fused edge GEMM + tanh + norm + scatter
    sgemm128<1><<<dim3(OUTF/128, E/128), 256>>>(ea, W2, 0, E, OUTF, EDF, rowI, colI);
    // 6. self loops + mean + bias + sigmoid -> seq
    seq_kernel<<<NN*OUTF/256, 256>>>(bias);
    // 7. xp0 = seq @ W_ih0^T   [8192 x 1024]
    sgemm128<0><<<dim3(4*HID_/128, NN/128), 256>>>((const float*)p_seq, W_ih0, (float*)p_xp0,
                                                   NN, 4*HID_, OUTF, 0, 0);
    // 8. persistent warp-autonomous LSTM (16 + 32 + 32 CTAs)
    lstm_kernel<<<80, 256>>>(W_hh0, W_ih1, W_hh1, W_ih2, W_hh2);
    // 9. pooling + big linear
    pool_lin_kernel<<<PPOOL/512, 256>>>(linW);
    // 10. tail + softmax
    final_kernel<<<1, 256>>>(linW, linb, out);
}